// round 5
// baseline (speedup 1.0000x reference)
#include <cuda_runtime.h>
#include <cuda_fp16.h>
#include <math.h>

#define NN 5000
#define TT 100
#define INDIM 32
#define FEAT 64
#define HIDD 64
#define OUTD 8
#define NHEADS 4
#define EE 160000
#define FIN 72
#define NTILES 260   // 20 row-tiles (256 nodes) x 13 col-chunks (64)

// ---------------- scratch (device globals; POD types only) -----------------
__device__ float        g_emb[(size_t)TT * NN * FEAT];        // [T][N][64]
__device__ float        g_q[(size_t)NN * 256];                // fp32 q
__device__ float        g_skip[(size_t)NN * 64];              // fp32 skip
__device__ unsigned int g_kh[(size_t)NN * 128];               // fp16 k (2/uint)
__device__ unsigned int g_vh[(size_t)NN * 128];               // fp16 v (2/uint)
__device__ float        g_theta[(size_t)(TT + 1) * NN * OUTD];// [T+1][N][8]
__device__ int          g_cnt[NN];
__device__ int          g_rowptr[NN + 1];
__device__ int          g_cursor[NN];
__device__ int          g_csrsrc[EE];
__device__ volatile unsigned int g_bar_gen;
__device__ unsigned int g_bar_cnt;

__device__ __forceinline__ float fsig(float x) {
    return __fdividef(1.f, 1.f + __expf(-x));
}
__device__ __forceinline__ float ftanh(float x) {
    return 2.f * fsig(2.f * x) - 1.f;
}

// software grid barrier: valid because grid == #SMs -> all blocks co-resident
__device__ __forceinline__ void grid_sync() {
    __syncthreads();
    if (threadIdx.x == 0) {
        unsigned int gen = g_bar_gen;
        __threadfence();
        unsigned int arr = atomicAdd(&g_bar_cnt, 1);
        if (arr == gridDim.x - 1) {
            atomicExch(&g_bar_cnt, 0);
            __threadfence();
            g_bar_gen = gen + 1;
        } else {
            while (g_bar_gen == gen) {}
            __threadfence();
        }
    }
    __syncthreads();
}

// ---------------- CSR build ------------------------------------------------
__global__ void k_init() {
    int i = blockIdx.x * 256 + threadIdx.x;
    if (i < NN) g_cnt[i] = 0;
    if (i < NN * OUTD) g_theta[i] = 0.f;
    if (i == 0) { g_bar_cnt = 0; g_bar_gen = 0; }
}

__global__ void k_count(const int* __restrict__ ei) {
    int e = blockIdx.x * 256 + threadIdx.x;
    if (e < EE) atomicAdd(&g_cnt[ei[EE + e]], 1);
}

__global__ void k_scan() {
    __shared__ int ss[256];
    int tid = threadIdx.x;
    int i0 = tid * 20;
    int sum = 0;
    for (int i = i0; i < i0 + 20 && i < NN; i++) sum += g_cnt[i];
    ss[tid] = sum;
    __syncthreads();
    if (tid == 0) {
        int run = 0;
        for (int i = 0; i < 256; i++) { int v = ss[i]; ss[i] = run; run += v; }
    }
    __syncthreads();
    int run = ss[tid];
    for (int i = i0; i < i0 + 20 && i < NN; i++) {
        g_rowptr[i] = run;
        g_cursor[i] = run;
        run += g_cnt[i];
    }
    if (tid == 255) g_rowptr[NN] = run;
}

__global__ void k_scatter(const int* __restrict__ ei) {
    int e = blockIdx.x * 256 + threadIdx.x;
    if (e < EE) {
        int d = ei[EE + e];
        int pos = atomicAdd(&g_cursor[d], 1);
        g_csrsrc[pos] = ei[e];
    }
}

// ---------------- LSTM: 4 nodes per warp, weights in smem ------------------
__global__ void k_lstm(const float* __restrict__ x,
                       const float* __restrict__ Wih,
                       const float* __restrict__ Whh,
                       const float* __restrict__ bih,
                       const float* __restrict__ bhh) {
    extern __shared__ float sm[];
    float* sWih = sm;                          // 32*256
    float* sWhh = sWih + 32 * 256;             // 64*256
    float* sB   = sWhh + 64 * 256;             // 256
    float* sX   = sB + 256;                    // 10 warps * 4 * 32
    float* sH   = sX + 10 * 4 * 32;            // 10 * 4 * 64
    float* sG   = sH + 10 * 4 * 64;            // 10 * 4 * 256

    int tid = threadIdx.x;
    for (int i = tid; i < 32 * 256; i += 320) sWih[i] = Wih[i];
    for (int i = tid; i < 64 * 256; i += 320) sWhh[i] = Whh[i];
    for (int i = tid; i < 256; i += 320) sB[i] = bih[i] + bhh[i];
    __syncthreads();

    int wid = tid >> 5, l = tid & 31;
    int nodeBase = (blockIdx.x * 10 + wid) * 4;
    float* wX = sX + wid * 4 * 32;
    float* wH = sH + wid * 4 * 64;
    float* wG = sG + wid * 4 * 256;
    int mloc = l >> 3, dbase = (l & 7) * 8;
    int col = l * 8;

    float c[8];
#pragma unroll
    for (int j = 0; j < 8; j++) { c[j] = 0.f; wH[mloc * 64 + dbase + j] = 0.f; }
    __syncwarp();

    for (int t = 0; t < TT; t++) {
#pragma unroll
        for (int s = 0; s < 4; s++)
            wX[s * 32 + l] = x[((size_t)(nodeBase + s) * TT + t) * INDIM + l];
        __syncwarp();

        float a[4][8];
#pragma unroll
        for (int m = 0; m < 4; m++)
#pragma unroll
            for (int j = 0; j < 8; j++) a[m][j] = sB[col + j];

#pragma unroll 4
        for (int kk = 0; kk < 32; kk++) {
            float4 w0 = *(const float4*)(sWih + kk * 256 + col);
            float4 w1 = *(const float4*)(sWih + kk * 256 + col + 4);
            float wv[8] = {w0.x, w0.y, w0.z, w0.w, w1.x, w1.y, w1.z, w1.w};
#pragma unroll
            for (int m = 0; m < 4; m++) {
                float xv = wX[m * 32 + kk];
#pragma unroll
                for (int j = 0; j < 8; j++) a[m][j] += xv * wv[j];
            }
        }
#pragma unroll 4
        for (int kk = 0; kk < 64; kk++) {
            float4 w0 = *(const float4*)(sWhh + kk * 256 + col);
            float4 w1 = *(const float4*)(sWhh + kk * 256 + col + 4);
            float wv[8] = {w0.x, w0.y, w0.z, w0.w, w1.x, w1.y, w1.z, w1.w};
#pragma unroll
            for (int m = 0; m < 4; m++) {
                float hv = wH[m * 64 + kk];
#pragma unroll
                for (int j = 0; j < 8; j++) a[m][j] += hv * wv[j];
            }
        }
        __syncwarp();
#pragma unroll
        for (int m = 0; m < 4; m++) {
            *(float4*)(wG + m * 256 + col)     = make_float4(a[m][0], a[m][1], a[m][2], a[m][3]);
            *(float4*)(wG + m * 256 + col + 4) = make_float4(a[m][4], a[m][5], a[m][6], a[m][7]);
        }
        __syncwarp();
        const float* gp = wG + mloc * 256;
        float hj[8];
#pragma unroll
        for (int j = 0; j < 8; j++) {
            float iv = fsig(gp[0 * 64 + dbase + j]);
            float fv = fsig(gp[1 * 64 + dbase + j]);
            float gv = ftanh(gp[2 * 64 + dbase + j]);
            float ov = fsig(gp[3 * 64 + dbase + j]);
            c[j] = fv * c[j] + iv * gv;
            hj[j] = ov * ftanh(c[j]);
        }
#pragma unroll
        for (int j = 0; j < 8; j++) wH[mloc * 64 + dbase + j] = hj[j];
        size_t eb = ((size_t)t * NN + (nodeBase + mloc)) * FEAT + dbase;
        *(float4*)(g_emb + eb)     = make_float4(hj[0], hj[1], hj[2], hj[3]);
        *(float4*)(g_emb + eb + 4) = make_float4(hj[4], hj[5], hj[6], hj[7]);
        __syncwarp();
    }
}

// ---------------- fp16 helpers for edge phase ------------------------------
__device__ __forceinline__ float dot8h(const float* q, uint4 r) {
    union { uint4 u; __half2 h[4]; } pk; pk.u = r;
    float2 f0 = __half22float2(pk.h[0]);
    float2 f1 = __half22float2(pk.h[1]);
    float2 f2 = __half22float2(pk.h[2]);
    float2 f3 = __half22float2(pk.h[3]);
    return q[0]*f0.x + q[1]*f0.y + q[2]*f1.x + q[3]*f1.y
         + q[4]*f2.x + q[5]*f2.y + q[6]*f3.x + q[7]*f3.y;
}
__device__ __forceinline__ void acc8h(float* acc, float p, uint4 r) {
    union { uint4 u; __half2 h[4]; } pk; pk.u = r;
    float2 f0 = __half22float2(pk.h[0]);
    float2 f1 = __half22float2(pk.h[1]);
    float2 f2 = __half22float2(pk.h[2]);
    float2 f3 = __half22float2(pk.h[3]);
    acc[0] += p * f0.x; acc[1] += p * f0.y;
    acc[2] += p * f1.x; acc[3] += p * f1.y;
    acc[4] += p * f2.x; acc[5] += p * f2.y;
    acc[6] += p * f3.x; acc[7] += p * f3.y;
}

// ---------------- persistent step kernel: all 100 steps --------------------
// grid = #SMs, 256 threads, 1 block/SM co-resident -> software grid barrier.
// Phase A: qkvs GEMM, 260 tiles (256 nodes x 64 cols, 8x8 per thread).
// Phase B: edge attention + epilogue, one warp per dst node, strided.
__global__ void k_steps(const float* __restrict__ Wq, const float* __restrict__ bq,
                        const float* __restrict__ Wk, const float* __restrict__ bk,
                        const float* __restrict__ Wv, const float* __restrict__ bv,
                        const float* __restrict__ Wsk, const float* __restrict__ bsk,
                        const float* __restrict__ Wmlp) {
    extern __shared__ float sm[];
    float* sW = sm;                 // [72][64]
    float* sH = sm + 72 * 64;       // [72][256]
    __shared__ float sWm[512];      // transposed Wmlp: sWm[o*64 + d]
    __shared__ float sB[64];

    int tid = threadIdx.x;
    for (int i = tid; i < 512; i += 256) {
        int d = i >> 3, o = i & 7;
        sWm[o * 64 + d] = Wmlp[i];
    }
    int wid = tid >> 5, l = tid & 31;
    int nwarps = gridDim.x * 8;

    for (int t = 0; t < TT; t++) {
        // -------- phase A: [emb_t | theta_t] @ [Wq|Wk|Wv|Wskip] ----------
        for (int tile = blockIdx.x; tile < NTILES; tile += gridDim.x) {
            int rowt = tile / 13, chunk = tile - rowt * 13;
            const float* Wsrc; const float* bsrc; int cofs, width;
            if (chunk < 4)       { Wsrc = Wq;  bsrc = bq;  cofs = chunk * 64;       width = 256; }
            else if (chunk < 8)  { Wsrc = Wk;  bsrc = bk;  cofs = (chunk - 4) * 64; width = 256; }
            else if (chunk < 12) { Wsrc = Wv;  bsrc = bv;  cofs = (chunk - 8) * 64; width = 256; }
            else                 { Wsrc = Wsk; bsrc = bsk; cofs = 0;                width = 64;  }

            for (int i = tid; i < 72 * 64; i += 256) {
                int k = i >> 6, c2 = i & 63;
                sW[i] = Wsrc[k * width + cofs + c2];
            }
            if (tid < 64) sB[tid] = bsrc[cofs + tid];

            int nb0 = rowt * 256;
            for (int i = tid; i < 256 * 72; i += 256) {
                int r = i / 72, k = i - r * 72;
                int node = nb0 + r;
                float v = 0.f;
                if (node < NN)
                    v = (k < 64) ? g_emb[((size_t)t * NN + node) * 64 + k]
                                 : g_theta[((size_t)t * NN + node) * 8 + (k - 64)];
                sH[k * 256 + r] = v;
            }
            __syncthreads();

            int cc = tid & 7, rr = tid >> 3;   // 8 col x 32 row groups
            float acc[8][8] = {};
#pragma unroll 4
            for (int k = 0; k < 72; k++) {
                float4 a0 = *(const float4*)(sH + k * 256 + rr * 8);
                float4 a1 = *(const float4*)(sH + k * 256 + rr * 8 + 4);
                float4 b0 = *(const float4*)(sW + k * 64 + cc * 8);
                float4 b1 = *(const float4*)(sW + k * 64 + cc * 8 + 4);
                float am[8] = {a0.x, a0.y, a0.z, a0.w, a1.x, a1.y, a1.z, a1.w};
                float bm[8] = {b0.x, b0.y, b0.z, b0.w, b1.x, b1.y, b1.z, b1.w};
#pragma unroll
                for (int i = 0; i < 8; i++)
#pragma unroll
                    for (int j = 0; j < 8; j++) acc[i][j] += am[i] * bm[j];
            }
            float bb[8];
#pragma unroll
            for (int j = 0; j < 8; j++) bb[j] = sB[cc * 8 + j];

#pragma unroll
            for (int i = 0; i < 8; i++) {
                int node = nb0 + rr * 8 + i;
                if (node >= NN) break;
                float o[8];
#pragma unroll
                for (int j = 0; j < 8; j++) o[j] = acc[i][j] + bb[j];
                if (chunk < 4) {
                    float* dst = g_q + (size_t)node * 256 + chunk * 64 + cc * 8;
                    *(float4*)dst       = make_float4(o[0], o[1], o[2], o[3]);
                    *(float4*)(dst + 4) = make_float4(o[4], o[5], o[6], o[7]);
                } else if (chunk < 12) {
                    unsigned int* dst = (chunk < 8)
                        ? g_kh + (size_t)node * 128 + (chunk - 4) * 32 + cc * 4
                        : g_vh + (size_t)node * 128 + (chunk - 8) * 32 + cc * 4;
                    union { uint4 u; __half2 h[4]; } pk;
                    pk.h[0] = __floats2half2_rn(o[0], o[1]);
                    pk.h[1] = __floats2half2_rn(o[2], o[3]);
                    pk.h[2] = __floats2half2_rn(o[4], o[5]);
                    pk.h[3] = __floats2half2_rn(o[6], o[7]);
                    *(uint4*)dst = pk.u;
                } else {
                    float* dst = g_skip + (size_t)node * 64 + cc * 8;
                    *(float4*)dst       = make_float4(o[0], o[1], o[2], o[3]);
                    *(float4*)(dst + 4) = make_float4(o[4], o[5], o[6], o[7]);
                }
            }
            __syncthreads();
        }
        grid_sync();

        // -------- phase B: edge attention + tanh + Wmlp ------------------
        for (int n = blockIdx.x * 8 + wid; n < NN; n += nwarps) {
            float q[8];
            {
                const float* qp = g_q + (size_t)n * 256 + l * 8;
                float4 q0 = *(const float4*)qp, q1 = *(const float4*)(qp + 4);
                q[0]=q0.x; q[1]=q0.y; q[2]=q0.z; q[3]=q0.w;
                q[4]=q1.x; q[5]=q1.y; q[6]=q1.z; q[7]=q1.w;
            }
            int s = g_rowptr[n], e = g_rowptr[n + 1];
            float den = 0.f;
            float acc[8] = {};
            int koff = l * 4;
            int i = s;
            for (; i + 4 <= e; i += 4) {
                int s0 = g_csrsrc[i],     s1 = g_csrsrc[i + 1];
                int s2 = g_csrsrc[i + 2], s3 = g_csrsrc[i + 3];
                uint4 k0 = *(const uint4*)(g_kh + (size_t)s0 * 128 + koff);
                uint4 k1 = *(const uint4*)(g_kh + (size_t)s1 * 128 + koff);
                uint4 k2 = *(const uint4*)(g_kh + (size_t)s2 * 128 + koff);
                uint4 k3 = *(const uint4*)(g_kh + (size_t)s3 * 128 + koff);
                uint4 v0 = *(const uint4*)(g_vh + (size_t)s0 * 128 + koff);
                uint4 v1 = *(const uint4*)(g_vh + (size_t)s1 * 128 + koff);
                uint4 v2 = *(const uint4*)(g_vh + (size_t)s2 * 128 + koff);
                uint4 v3 = *(const uint4*)(g_vh + (size_t)s3 * 128 + koff);
                float d0 = dot8h(q, k0), d1 = dot8h(q, k1);
                float d2 = dot8h(q, k2), d3 = dot8h(q, k3);
#pragma unroll
                for (int r = 1; r <= 4; r <<= 1) {
                    d0 += __shfl_xor_sync(0xffffffffu, d0, r);
                    d1 += __shfl_xor_sync(0xffffffffu, d1, r);
                    d2 += __shfl_xor_sync(0xffffffffu, d2, r);
                    d3 += __shfl_xor_sync(0xffffffffu, d3, r);
                }
                float p0 = __expf(d0 * 0.125f), p1 = __expf(d1 * 0.125f);
                float p2 = __expf(d2 * 0.125f), p3 = __expf(d3 * 0.125f);
                den += (p0 + p1) + (p2 + p3);
                acc8h(acc, p0, v0); acc8h(acc, p1, v1);
                acc8h(acc, p2, v2); acc8h(acc, p3, v3);
            }
            for (; i < e; i++) {
                int s0 = g_csrsrc[i];
                uint4 k0 = *(const uint4*)(g_kh + (size_t)s0 * 128 + koff);
                uint4 v0 = *(const uint4*)(g_vh + (size_t)s0 * 128 + koff);
                float d0 = dot8h(q, k0);
#pragma unroll
                for (int r = 1; r <= 4; r <<= 1)
                    d0 += __shfl_xor_sync(0xffffffffu, d0, r);
                float p0 = __expf(d0 * 0.125f);
                den += p0;
                acc8h(acc, p0, v0);
            }

            float inv = 0.25f * __fdividef(1.f, fmaxf(den, 1e-16f));
            float outv[8];
#pragma unroll
            for (int j = 0; j < 8; j++) {
                float ag = acc[j] * inv;
                ag += __shfl_xor_sync(0xffffffffu, ag, 8);
                ag += __shfl_xor_sync(0xffffffffu, ag, 16);
                outv[j] = ag;
            }
            int dbase = (l & 7) * 8;
            const float* skp = g_skip + (size_t)n * 64 + dbase;
            float4 s0f = *(const float4*)skp, s1f = *(const float4*)(skp + 4);
            float sk[8] = {s0f.x, s0f.y, s0f.z, s0f.w, s1f.x, s1f.y, s1f.z, s1f.w};
            float tv[8];
#pragma unroll
            for (int j = 0; j < 8; j++) tv[j] = ftanh(outv[j] + sk[j]);

            float p8[8];
#pragma unroll
            for (int o = 0; o < 8; o++) {
                const float* wr = sWm + o * 64 + dbase;
                float4 w0 = *(const float4*)wr, w1 = *(const float4*)(wr + 4);
                p8[o] = tv[0]*w0.x + tv[1]*w0.y + tv[2]*w0.z + tv[3]*w0.w
                      + tv[4]*w1.x + tv[5]*w1.y + tv[6]*w1.z + tv[7]*w1.w;
            }
#pragma unroll
            for (int o = 0; o < 8; o++) {
                p8[o] += __shfl_xor_sync(0xffffffffu, p8[o], 1);
                p8[o] += __shfl_xor_sync(0xffffffffu, p8[o], 2);
                p8[o] += __shfl_xor_sync(0xffffffffu, p8[o], 4);
            }
            if (l < 8) g_theta[((size_t)(t + 1) * NN + n) * 8 + l] = p8[l];
        }
        grid_sync();
    }
}

// ---------------- final postprocess ----------------------------------------
__global__ void k_post(float* __restrict__ out) {
    int idx = blockIdx.x * 256 + threadIdx.x;
    if (idx >= NN * TT) return;
    int n = idx / TT, t = idx - n * TT;
    const float* th = g_theta + ((size_t)(t + 1) * NN + n) * 8;
    float4 a0 = *(const float4*)th, a1 = *(const float4*)(th + 4);
    float v5 = a1.y, v6 = a1.z, v7 = a1.w;
    float s5 = 1.f / (1.f + expf(-v5));
    float s6 = 1.f / (1.f + expf(-v6));
    float a = s5 * s6;
    float b = s5 - a;
    float cpl = fmaxf(v7, 0.f) + log1pf(expf(-fabsf(v7)));
    float* op = out + ((size_t)n * TT + t) * 8;
    *(float4*)op       = make_float4(a0.x, a0.y, a0.z, a0.w);
    *(float4*)(op + 4) = make_float4(a1.x, a, b, cpl);
}

// ---------------- launch ----------------------------------------------------
extern "C" void kernel_launch(void* const* d_in, const int* in_sizes, int n_in,
                              void* d_out, int out_size) {
    const float* x    = (const float*)d_in[0];
    const int*   ei   = (const int*)d_in[1];
    const float* Wih  = (const float*)d_in[2];
    const float* Whh  = (const float*)d_in[3];
    const float* bih  = (const float*)d_in[4];
    const float* bhh  = (const float*)d_in[5];
    const float* Wq   = (const float*)d_in[6];
    const float* bq   = (const float*)d_in[7];
    const float* Wk   = (const float*)d_in[8];
    const float* bk   = (const float*)d_in[9];
    const float* Wv   = (const float*)d_in[10];
    const float* bv   = (const float*)d_in[11];
    const float* Wsk  = (const float*)d_in[12];
    const float* bsk  = (const float*)d_in[13];
    const float* Wmlp = (const float*)d_in[14];

    size_t lsmem = (size_t)(32*256 + 64*256 + 256 + 10*4*32 + 10*4*64 + 10*4*256) * sizeof(float);
    cudaFuncSetAttribute(k_lstm, cudaFuncAttributeMaxDynamicSharedMemorySize, (int)lsmem);
    size_t ssmem = (size_t)(72*64 + 72*256) * sizeof(float);   // 92160 B
    cudaFuncSetAttribute(k_steps, cudaFuncAttributeMaxDynamicSharedMemorySize, (int)ssmem);

    int dev = 0, nsm = 148;
    cudaGetDevice(&dev);
    cudaDeviceGetAttribute(&nsm, cudaDevAttrMultiProcessorCount, dev);

    k_init<<<(NN * OUTD + 255) / 256, 256>>>();
    k_count<<<(EE + 255) / 256, 256>>>(ei);
    k_scan<<<1, 256>>>();
    k_scatter<<<(EE + 255) / 256, 256>>>(ei);
    k_lstm<<<125, 320, lsmem>>>(x, Wih, Whh, bih, bhh);
    k_steps<<<nsm, 256, ssmem>>>(Wq, bq, Wk, bk, Wv, bv, Wsk, bsk, Wmlp);
    k_post<<<(NN * TT + 255) / 256, 256>>>((float*)d_out);
}

// round 6
// speedup vs baseline: 2.1410x; 2.1410x over previous
#include <cuda_runtime.h>
#include <cuda_fp16.h>
#include <math.h>

#define NN 5000
#define TT 100
#define INDIM 32
#define FEAT 64
#define HIDD 64
#define OUTD 8
#define NHEADS 4
#define EE 160000
#define FIN 72
#define SSTR 88   // smem half-element stride (conflict-free: 44 words, 12-pattern)

// ---------------- scratch (device globals; POD types only) -----------------
__device__ float        g_emb[(size_t)TT * NN * FEAT];        // [T][N][64]
__device__ float        g_q[(size_t)NN * 256];                // fp32 q
__device__ float        g_skip[(size_t)NN * 64];              // fp32 skip
__device__ unsigned int g_kh[(size_t)NN * 128];               // fp16 k (2/uint)
__device__ unsigned int g_vh[(size_t)NN * 128];               // fp16 v (2/uint)
__device__ float        g_theta[(size_t)(TT + 1) * NN * OUTD];// [T+1][N][8]
__device__ int          g_cnt[NN];
__device__ int          g_rowptr[NN + 1];
__device__ int          g_cursor[NN];
__device__ int          g_csrsrc[EE];

__device__ __forceinline__ float fsig(float x) {
    return __fdividef(1.f, 1.f + __expf(-x));
}
__device__ __forceinline__ float ftanh(float x) {
    return 2.f * fsig(2.f * x) - 1.f;
}

// ---------------- CSR build ------------------------------------------------
__global__ void k_init() {
    int i = blockIdx.x * 256 + threadIdx.x;
    if (i < NN) g_cnt[i] = 0;
    if (i < NN * OUTD) g_theta[i] = 0.f;
}

__global__ void k_count(const int* __restrict__ ei) {
    int e = blockIdx.x * 256 + threadIdx.x;
    if (e < EE) atomicAdd(&g_cnt[ei[EE + e]], 1);
}

__global__ void k_scan() {
    __shared__ int ss[256];
    int tid = threadIdx.x;
    int i0 = tid * 20;
    int sum = 0;
    for (int i = i0; i < i0 + 20 && i < NN; i++) sum += g_cnt[i];
    ss[tid] = sum;
    __syncthreads();
    if (tid == 0) {
        int run = 0;
        for (int i = 0; i < 256; i++) { int v = ss[i]; ss[i] = run; run += v; }
    }
    __syncthreads();
    int run = ss[tid];
    for (int i = i0; i < i0 + 20 && i < NN; i++) {
        g_rowptr[i] = run;
        g_cursor[i] = run;
        run += g_cnt[i];
    }
    if (tid == 255) g_rowptr[NN] = run;
}

__global__ void k_scatter(const int* __restrict__ ei) {
    int e = blockIdx.x * 256 + threadIdx.x;
    if (e < EE) {
        int d = ei[EE + e];
        int pos = atomicAdd(&g_cursor[d], 1);
        g_csrsrc[pos] = ei[e];
    }
}

// ---------------- LSTM: 4 nodes per warp, weights in smem ------------------
__global__ void k_lstm(const float* __restrict__ x,
                       const float* __restrict__ Wih,
                       const float* __restrict__ Whh,
                       const float* __restrict__ bih,
                       const float* __restrict__ bhh) {
    extern __shared__ float sm[];
    float* sWih = sm;                          // 32*256
    float* sWhh = sWih + 32 * 256;             // 64*256
    float* sB   = sWhh + 64 * 256;             // 256
    float* sX   = sB + 256;                    // 10 warps * 4 * 32
    float* sH   = sX + 10 * 4 * 32;            // 10 * 4 * 64
    float* sG   = sH + 10 * 4 * 64;            // 10 * 4 * 256

    int tid = threadIdx.x;
    for (int i = tid; i < 32 * 256; i += 320) sWih[i] = Wih[i];
    for (int i = tid; i < 64 * 256; i += 320) sWhh[i] = Whh[i];
    for (int i = tid; i < 256; i += 320) sB[i] = bih[i] + bhh[i];
    __syncthreads();

    int wid = tid >> 5, l = tid & 31;
    int nodeBase = (blockIdx.x * 10 + wid) * 4;
    float* wX = sX + wid * 4 * 32;
    float* wH = sH + wid * 4 * 64;
    float* wG = sG + wid * 4 * 256;
    int mloc = l >> 3, dbase = (l & 7) * 8;
    int col = l * 8;

    float c[8];
#pragma unroll
    for (int j = 0; j < 8; j++) { c[j] = 0.f; wH[mloc * 64 + dbase + j] = 0.f; }
    __syncwarp();

    for (int t = 0; t < TT; t++) {
#pragma unroll
        for (int s = 0; s < 4; s++)
            wX[s * 32 + l] = x[((size_t)(nodeBase + s) * TT + t) * INDIM + l];
        __syncwarp();

        float a[4][8];
#pragma unroll
        for (int m = 0; m < 4; m++)
#pragma unroll
            for (int j = 0; j < 8; j++) a[m][j] = sB[col + j];

#pragma unroll 4
        for (int kk = 0; kk < 32; kk++) {
            float4 w0 = *(const float4*)(sWih + kk * 256 + col);
            float4 w1 = *(const float4*)(sWih + kk * 256 + col + 4);
            float wv[8] = {w0.x, w0.y, w0.z, w0.w, w1.x, w1.y, w1.z, w1.w};
#pragma unroll
            for (int m = 0; m < 4; m++) {
                float xv = wX[m * 32 + kk];
#pragma unroll
                for (int j = 0; j < 8; j++) a[m][j] += xv * wv[j];
            }
        }
#pragma unroll 4
        for (int kk = 0; kk < 64; kk++) {
            float4 w0 = *(const float4*)(sWhh + kk * 256 + col);
            float4 w1 = *(const float4*)(sWhh + kk * 256 + col + 4);
            float wv[8] = {w0.x, w0.y, w0.z, w0.w, w1.x, w1.y, w1.z, w1.w};
#pragma unroll
            for (int m = 0; m < 4; m++) {
                float hv = wH[m * 64 + kk];
#pragma unroll
                for (int j = 0; j < 8; j++) a[m][j] += hv * wv[j];
            }
        }
        __syncwarp();
#pragma unroll
        for (int m = 0; m < 4; m++) {
            *(float4*)(wG + m * 256 + col)     = make_float4(a[m][0], a[m][1], a[m][2], a[m][3]);
            *(float4*)(wG + m * 256 + col + 4) = make_float4(a[m][4], a[m][5], a[m][6], a[m][7]);
        }
        __syncwarp();
        const float* gp = wG + mloc * 256;
        float hj[8];
#pragma unroll
        for (int j = 0; j < 8; j++) {
            float iv = fsig(gp[0 * 64 + dbase + j]);
            float fv = fsig(gp[1 * 64 + dbase + j]);
            float gv = ftanh(gp[2 * 64 + dbase + j]);
            float ov = fsig(gp[3 * 64 + dbase + j]);
            c[j] = fv * c[j] + iv * gv;
            hj[j] = ov * ftanh(c[j]);
        }
#pragma unroll
        for (int j = 0; j < 8; j++) wH[mloc * 64 + dbase + j] = hj[j];
        size_t eb = ((size_t)t * NN + (nodeBase + mloc)) * FEAT + dbase;
        *(float4*)(g_emb + eb)     = make_float4(hj[0], hj[1], hj[2], hj[3]);
        *(float4*)(g_emb + eb + 4) = make_float4(hj[4], hj[5], hj[6], hj[7]);
        __syncwarp();
    }
}

// ---------------- per-step GEMM via tensor cores (HMMA m16n8k16) -----------
// C[5000x832] = H[5000x72] @ W[72x832], fp16 inputs, fp32 accumulate.
// Block: 256 thr = 8 warps (4x2), tile 128 rows x 64 cols, K padded to 80.
// Grid (13, 40): chunks 0-3 q, 4-7 k, 8-11 v, 12 skip.
__device__ __forceinline__ void mma16816(float* c, const unsigned* a, const unsigned* b) {
    asm volatile(
        "mma.sync.aligned.m16n8k16.row.col.f32.f16.f16.f32 "
        "{%0,%1,%2,%3}, {%4,%5,%6,%7}, {%8,%9}, {%0,%1,%2,%3};"
        : "+f"(c[0]), "+f"(c[1]), "+f"(c[2]), "+f"(c[3])
        : "r"(a[0]), "r"(a[1]), "r"(a[2]), "r"(a[3]), "r"(b[0]), "r"(b[1]));
}

__global__ void k_gemm(int t,
                       const float* __restrict__ Wq, const float* __restrict__ bq,
                       const float* __restrict__ Wk, const float* __restrict__ bk,
                       const float* __restrict__ Wv, const float* __restrict__ bv,
                       const float* __restrict__ Wsk, const float* __restrict__ bsk) {
    __shared__ __align__(16) __half sA[128 * SSTR];   // H tile [row][k]
    __shared__ __align__(16) __half sBt[64 * SSTR];   // W chunk transposed [n][k]
    __shared__ float sBias[64];

    int chunk = blockIdx.x;
    const float* Wsrc; const float* bsrc; int cofs, width;
    if (chunk < 4)       { Wsrc = Wq;  bsrc = bq;  cofs = chunk * 64;       width = 256; }
    else if (chunk < 8)  { Wsrc = Wk;  bsrc = bk;  cofs = (chunk - 4) * 64; width = 256; }
    else if (chunk < 12) { Wsrc = Wv;  bsrc = bv;  cofs = (chunk - 8) * 64; width = 256; }
    else                 { Wsrc = Wsk; bsrc = bsk; cofs = 0;                width = 64;  }

    int tid = threadIdx.x;
    int nb0 = blockIdx.y * 128;

    // stage H tile fp32->fp16 (k >= 72 zero-padded)
    for (int i = tid; i < 128 * 80; i += 256) {
        int r = i / 80, k = i - r * 80;
        int node = nb0 + r;
        float v = 0.f;
        if (node < NN && k < 72)
            v = (k < 64) ? g_emb[((size_t)t * NN + node) * 64 + k]
                         : g_theta[((size_t)t * NN + node) * 8 + (k - 64)];
        sA[r * SSTR + k] = __float2half(v);
    }
    // stage W chunk transposed [n][k] (coalesced gmem reads along n)
    for (int i = tid; i < 80 * 64; i += 256) {
        int k = i >> 6, n = i & 63;
        float v = (k < 72) ? Wsrc[k * width + cofs + n] : 0.f;
        sBt[n * SSTR + k] = __float2half(v);
    }
    if (tid < 64) sBias[tid] = bsrc[cofs + tid];
    __syncthreads();

    int wid = tid >> 5, l = tid & 31;
    int wr = wid >> 1, wc = wid & 1;       // warp grid 4 (rows) x 2 (cols)
    int g = l >> 2, tg = l & 3;

    float c[2][4][4];
#pragma unroll
    for (int ms = 0; ms < 2; ms++)
#pragma unroll
        for (int ns = 0; ns < 4; ns++)
#pragma unroll
            for (int j = 0; j < 4; j++) c[ms][ns][j] = 0.f;

#pragma unroll
    for (int ks = 0; ks < 5; ks++) {
        int kb = ks * 16;
        unsigned a[2][4], b[4][2];
#pragma unroll
        for (int ms = 0; ms < 2; ms++) {
            int row = wr * 32 + ms * 16 + g;
            const __half* p0 = sA + row * SSTR + kb + tg * 2;
            const __half* p1 = sA + (row + 8) * SSTR + kb + tg * 2;
            a[ms][0] = *(const unsigned*)p0;
            a[ms][1] = *(const unsigned*)p1;
            a[ms][2] = *(const unsigned*)(p0 + 8);
            a[ms][3] = *(const unsigned*)(p1 + 8);
        }
#pragma unroll
        for (int ns = 0; ns < 4; ns++) {
            int n = wc * 32 + ns * 8 + g;
            const __half* p = sBt + n * SSTR + kb + tg * 2;
            b[ns][0] = *(const unsigned*)p;
            b[ns][1] = *(const unsigned*)(p + 8);
        }
#pragma unroll
        for (int ms = 0; ms < 2; ms++)
#pragma unroll
            for (int ns = 0; ns < 4; ns++)
                mma16816(c[ms][ns], a[ms], b[ns]);
    }

    // epilogue: bias add + store (q/skip fp32, k/v fp16)
#pragma unroll
    for (int ms = 0; ms < 2; ms++) {
        int row0 = nb0 + wr * 32 + ms * 16 + g;
#pragma unroll
        for (int ns = 0; ns < 4; ns++) {
            int col = wc * 32 + ns * 8 + tg * 2;
            float b0 = sBias[col], b1 = sBias[col + 1];
            float o0 = c[ms][ns][0] + b0, o1 = c[ms][ns][1] + b1;
            float o2 = c[ms][ns][2] + b0, o3 = c[ms][ns][3] + b1;
            if (chunk < 4) {
                if (row0 < NN)
                    *(float2*)(g_q + (size_t)row0 * 256 + chunk * 64 + col) = make_float2(o0, o1);
                if (row0 + 8 < NN)
                    *(float2*)(g_q + (size_t)(row0 + 8) * 256 + chunk * 64 + col) = make_float2(o2, o3);
            } else if (chunk < 12) {
                unsigned int* base = (chunk < 8) ? g_kh : g_vh;
                int cofs2 = ((chunk < 8) ? (chunk - 4) : (chunk - 8)) * 32 + (col >> 1);
                union { unsigned u; __half2 h; } p0, p1;
                p0.h = __floats2half2_rn(o0, o1);
                p1.h = __floats2half2_rn(o2, o3);
                if (row0 < NN)     base[(size_t)row0 * 128 + cofs2] = p0.u;
                if (row0 + 8 < NN) base[(size_t)(row0 + 8) * 128 + cofs2] = p1.u;
            } else {
                if (row0 < NN)
                    *(float2*)(g_skip + (size_t)row0 * 64 + col) = make_float2(o0, o1);
                if (row0 + 8 < NN)
                    *(float2*)(g_skip + (size_t)(row0 + 8) * 64 + col) = make_float2(o2, o3);
            }
        }
    }
}

// ---------------- per-step edge attention + epilogue -----------------------
__device__ __forceinline__ float dot8h(const float* q, uint4 r) {
    union { uint4 u; __half2 h[4]; } pk; pk.u = r;
    float2 f0 = __half22float2(pk.h[0]);
    float2 f1 = __half22float2(pk.h[1]);
    float2 f2 = __half22float2(pk.h[2]);
    float2 f3 = __half22float2(pk.h[3]);
    return q[0]*f0.x + q[1]*f0.y + q[2]*f1.x + q[3]*f1.y
         + q[4]*f2.x + q[5]*f2.y + q[6]*f3.x + q[7]*f3.y;
}
__device__ __forceinline__ void acc8h(float* acc, float p, uint4 r) {
    union { uint4 u; __half2 h[4]; } pk; pk.u = r;
    float2 f0 = __half22float2(pk.h[0]);
    float2 f1 = __half22float2(pk.h[1]);
    float2 f2 = __half22float2(pk.h[2]);
    float2 f3 = __half22float2(pk.h[3]);
    acc[0] += p * f0.x; acc[1] += p * f0.y;
    acc[2] += p * f1.x; acc[3] += p * f1.y;
    acc[4] += p * f2.x; acc[5] += p * f2.y;
    acc[6] += p * f3.x; acc[7] += p * f3.y;
}

__global__ void k_edge(int t, const float* __restrict__ Wmlp) {
    __shared__ float sWm[8 * 64];   // transposed Wmlp
    int tid = threadIdx.x;
    for (int i = tid; i < 512; i += 256) {
        int d = i >> 3, o = i & 7;
        sWm[o * 64 + d] = Wmlp[i];
    }
    __syncthreads();

    int wid = tid >> 5, l = tid & 31;
    int n = blockIdx.x * 8 + wid;                 // 625*8 = 5000

    float q[8];
    {
        const float* qp = g_q + (size_t)n * 256 + l * 8;
        float4 q0 = *(const float4*)qp, q1 = *(const float4*)(qp + 4);
        q[0]=q0.x; q[1]=q0.y; q[2]=q0.z; q[3]=q0.w;
        q[4]=q1.x; q[5]=q1.y; q[6]=q1.z; q[7]=q1.w;
    }
    int s = g_rowptr[n], e = g_rowptr[n + 1];
    float den = 0.f;
    float acc[8] = {};
    int koff = l * 4;
    int i = s;
    for (; i + 4 <= e; i += 4) {
        int s0 = g_csrsrc[i],     s1 = g_csrsrc[i + 1];
        int s2 = g_csrsrc[i + 2], s3 = g_csrsrc[i + 3];
        uint4 k0 = *(const uint4*)(g_kh + (size_t)s0 * 128 + koff);
        uint4 k1 = *(const uint4*)(g_kh + (size_t)s1 * 128 + koff);
        uint4 k2 = *(const uint4*)(g_kh + (size_t)s2 * 128 + koff);
        uint4 k3 = *(const uint4*)(g_kh + (size_t)s3 * 128 + koff);
        uint4 v0 = *(const uint4*)(g_vh + (size_t)s0 * 128 + koff);
        uint4 v1 = *(const uint4*)(g_vh + (size_t)s1 * 128 + koff);
        uint4 v2 = *(const uint4*)(g_vh + (size_t)s2 * 128 + koff);
        uint4 v3 = *(const uint4*)(g_vh + (size_t)s3 * 128 + koff);
        float d0 = dot8h(q, k0), d1 = dot8h(q, k1);
        float d2 = dot8h(q, k2), d3 = dot8h(q, k3);
#pragma unroll
        for (int r = 1; r <= 4; r <<= 1) {
            d0 += __shfl_xor_sync(0xffffffffu, d0, r);
            d1 += __shfl_xor_sync(0xffffffffu, d1, r);
            d2 += __shfl_xor_sync(0xffffffffu, d2, r);
            d3 += __shfl_xor_sync(0xffffffffu, d3, r);
        }
        float p0 = __expf(d0 * 0.125f), p1 = __expf(d1 * 0.125f);
        float p2 = __expf(d2 * 0.125f), p3 = __expf(d3 * 0.125f);
        den += (p0 + p1) + (p2 + p3);
        acc8h(acc, p0, v0); acc8h(acc, p1, v1);
        acc8h(acc, p2, v2); acc8h(acc, p3, v3);
    }
    for (; i < e; i++) {
        int s0 = g_csrsrc[i];
        uint4 k0 = *(const uint4*)(g_kh + (size_t)s0 * 128 + koff);
        uint4 v0 = *(const uint4*)(g_vh + (size_t)s0 * 128 + koff);
        float d0 = dot8h(q, k0);
#pragma unroll
        for (int r = 1; r <= 4; r <<= 1)
            d0 += __shfl_xor_sync(0xffffffffu, d0, r);
        float p0 = __expf(d0 * 0.125f);
        den += p0;
        acc8h(acc, p0, v0);
    }

    float inv = 0.25f * __fdividef(1.f, fmaxf(den, 1e-16f));
    float outv[8];
#pragma unroll
    for (int j = 0; j < 8; j++) {
        float ag = acc[j] * inv;
        ag += __shfl_xor_sync(0xffffffffu, ag, 8);
        ag += __shfl_xor_sync(0xffffffffu, ag, 16);
        outv[j] = ag;
    }
    int dbase = (l & 7) * 8;
    const float* skp = g_skip + (size_t)n * 64 + dbase;
    float4 s0f = *(const float4*)skp, s1f = *(const float4*)(skp + 4);
    float sk[8] = {s0f.x, s0f.y, s0f.z, s0f.w, s1f.x, s1f.y, s1f.z, s1f.w};
    float tv[8];
#pragma unroll
    for (int j = 0; j < 8; j++) tv[j] = ftanh(outv[j] + sk[j]);

    float p8[8];
#pragma unroll
    for (int o = 0; o < 8; o++) {
        const float* wr = sWm + o * 64 + dbase;
        float4 w0 = *(const float4*)wr, w1 = *(const float4*)(wr + 4);
        p8[o] = tv[0]*w0.x + tv[1]*w0.y + tv[2]*w0.z + tv[3]*w0.w
              + tv[4]*w1.x + tv[5]*w1.y + tv[6]*w1.z + tv[7]*w1.w;
    }
#pragma unroll
    for (int o = 0; o < 8; o++) {
        p8[o] += __shfl_xor_sync(0xffffffffu, p8[o], 1);
        p8[o] += __shfl_xor_sync(0xffffffffu, p8[o], 2);
        p8[o] += __shfl_xor_sync(0xffffffffu, p8[o], 4);
    }
    if (l < 8) g_theta[((size_t)(t + 1) * NN + n) * 8 + l] = p8[l];
}

// ---------------- final postprocess ----------------------------------------
__global__ void k_post(float* __restrict__ out) {
    int idx = blockIdx.x * 256 + threadIdx.x;
    if (idx >= NN * TT) return;
    int n = idx / TT, t = idx - n * TT;
    const float* th = g_theta + ((size_t)(t + 1) * NN + n) * 8;
    float4 a0 = *(const float4*)th, a1 = *(const float4*)(th + 4);
    float v5 = a1.y, v6 = a1.z, v7 = a1.w;
    float s5 = 1.f / (1.f + expf(-v5));
    float s6 = 1.f / (1.f + expf(-v6));
    float a = s5 * s6;
    float b = s5 - a;
    float cpl = fmaxf(v7, 0.f) + log1pf(expf(-fabsf(v7)));
    float* op = out + ((size_t)n * TT + t) * 8;
    *(float4*)op       = make_float4(a0.x, a0.y, a0.z, a0.w);
    *(float4*)(op + 4) = make_float4(a1.x, a, b, cpl);
}

// ---------------- launch ----------------------------------------------------
extern "C" void kernel_launch(void* const* d_in, const int* in_sizes, int n_in,
                              void* d_out, int out_size) {
    const float* x    = (const float*)d_in[0];
    const int*   ei   = (const int*)d_in[1];
    const float* Wih  = (const float*)d_in[2];
    const float* Whh  = (const float*)d_in[3];
    const float* bih  = (const float*)d_in[4];
    const float* bhh  = (const float*)d_in[5];
    const float* Wq   = (const float*)d_in[6];
    const float* bq   = (const float*)d_in[7];
    const float* Wk   = (const float*)d_in[8];
    const float* bk   = (const float*)d_in[9];
    const float* Wv   = (const float*)d_in[10];
    const float* bv   = (const float*)d_in[11];
    const float* Wsk  = (const float*)d_in[12];
    const float* bsk  = (const float*)d_in[13];
    const float* Wmlp = (const float*)d_in[14];

    size_t lsmem = (size_t)(32*256 + 64*256 + 256 + 10*4*32 + 10*4*64 + 10*4*256) * sizeof(float);
    cudaFuncSetAttribute(k_lstm, cudaFuncAttributeMaxDynamicSharedMemorySize, (int)lsmem);

    k_init<<<(NN * OUTD + 255) / 256, 256>>>();
    k_count<<<(EE + 255) / 256, 256>>>(ei);
    k_scan<<<1, 256>>>();
    k_scatter<<<(EE + 255) / 256, 256>>>(ei);
    k_lstm<<<125, 320, lsmem>>>(x, Wih, Whh, bih, bhh);

    for (int t = 0; t < TT; t++) {
        dim3 g(13, 40);
        k_gemm<<<g, 256>>>(t, Wq, bq, Wk, bk, Wv, bv, Wsk, bsk);
        k_edge<<<625, 256>>>(t, Wmlp);
    }
    k_post<<<(NN * TT + 255) / 256, 256>>>((float*)d_out);
}